// round 15
// baseline (speedup 1.0000x reference)
#include <cuda_runtime.h>

// ---------------- problem constants ----------------
#define T_STEPS 192
#define B_SZ    128
#define IN_SZ   512
#define R_SZ    1024
#define OUT_SZ  100
#define PS      64
#define BR      (B_SZ * R_SZ)          // 131072
#define SPK_ELEMS (T_STEPS * BR)       // 25165824
#define OUT_ELEMS (B_SZ * OUT_SZ)      // 12800
#define ALPHA 0.9f
#define BETA  0.9f

#define GK 256                 // K per split chunk (association FROZEN)
#define NSPLIT_MAX 8
#define TSTRIDE 68             // smem row stride (64 + pad)

// ---------------- device scratch ----------------
__device__ float g_cur[T_STEPS * BR];    // input projection (+b_in)
__device__ float g_spk[T_STEPS * BR];    // spike history fp32
__device__ float g_syn[BR];
__device__ float g_mem[BR];
__device__ float g_part[NSPLIT_MAX * BR];// split-K partials
__device__ float g_ro[B_SZ * 3 * R_SZ]; // readout input
__device__ unsigned g_cnt[T_STEPS * 32]; // per-(t, region) arrival counters

typedef unsigned long long ull;

__device__ __forceinline__ ull pack2(float lo, float hi) {
    ull r; asm("mov.b64 %0, {%1,%2};" : "=l"(r) : "f"(lo), "f"(hi)); return r;
}
__device__ __forceinline__ void fma2(ull &d, ull a, ull b) {
    asm("fma.rn.f32x2 %0, %1, %2, %0;" : "+l"(d) : "l"(a), "l"(b));
}
__device__ __forceinline__ float2 unpack2(ull v) {
    float2 r; asm("mov.b64 {%0,%1}, %2;" : "=f"(r.x), "=f"(r.y) : "l"(v)); return r;
}

// ---------------- init: zero syn/mem/counters ----------------
__global__ void k_init() {
    int i = blockIdx.x * blockDim.x + threadIdx.x;
    float4 z = make_float4(0.f, 0.f, 0.f, 0.f);
    *(float4*)(g_syn + i * 4) = z;
    *(float4*)(g_mem + i * 4) = z;
    if (blockIdx.x == 0) {
        for (int j = threadIdx.x; j < T_STEPS * 32; j += 256) g_cnt[j] = 0u;
    }
}

// ---------------- input projection GEMM (R1, known-correct) ----------------
__global__ void k_input_gemm(const float* __restrict__ X,
                             const float* __restrict__ Win,
                             const float* __restrict__ bin) {
    __shared__ float As[16][128];
    __shared__ float Bs[16][128];
    int tid = threadIdx.x;
    int n0 = blockIdx.x * 128;
    int m0 = blockIdx.y * 128;
    int p  = m0 >> 13;
    const float* A = X + (size_t)m0 * IN_SZ;
    const float* W = Win + (size_t)p * R_SZ * IN_SZ + (size_t)n0 * IN_SZ;

    int lr = tid >> 2;
    int lk = (tid & 3) * 4;
    int tx = tid & 15, ty = tid >> 4;

    ull acc[8][4];
#pragma unroll
    for (int i = 0; i < 8; i++)
#pragma unroll
        for (int j = 0; j < 4; j++) acc[i][j] = 0ULL;

    for (int k0 = 0; k0 < IN_SZ; k0 += 16) {
        float4 a0 = *(const float4*)(A + (size_t)lr * IN_SZ + k0 + lk);
        float4 a1 = *(const float4*)(A + (size_t)(lr + 64) * IN_SZ + k0 + lk);
        float4 b0 = *(const float4*)(W + (size_t)lr * IN_SZ + k0 + lk);
        float4 b1 = *(const float4*)(W + (size_t)(lr + 64) * IN_SZ + k0 + lk);
        __syncthreads();
        As[lk + 0][lr] = a0.x; As[lk + 1][lr] = a0.y; As[lk + 2][lr] = a0.z; As[lk + 3][lr] = a0.w;
        As[lk + 0][lr + 64] = a1.x; As[lk + 1][lr + 64] = a1.y; As[lk + 2][lr + 64] = a1.z; As[lk + 3][lr + 64] = a1.w;
        Bs[lk + 0][lr] = b0.x; Bs[lk + 1][lr] = b0.y; Bs[lk + 2][lr] = b0.z; Bs[lk + 3][lr] = b0.w;
        Bs[lk + 0][lr + 64] = b1.x; Bs[lk + 1][lr + 64] = b1.y; Bs[lk + 2][lr + 64] = b1.z; Bs[lk + 3][lr + 64] = b1.w;
        __syncthreads();
#pragma unroll
        for (int kk = 0; kk < 16; kk++) {
            float4 af0 = *(float4*)&As[kk][ty * 8];
            float4 af1 = *(float4*)&As[kk][ty * 8 + 4];
            float4 bf0 = *(float4*)&Bs[kk][tx * 8];
            float4 bf1 = *(float4*)&Bs[kk][tx * 8 + 4];
            ull b2[4] = { pack2(bf0.x, bf0.y), pack2(bf0.z, bf0.w),
                          pack2(bf1.x, bf1.y), pack2(bf1.z, bf1.w) };
            float am[8] = { af0.x, af0.y, af0.z, af0.w, af1.x, af1.y, af1.z, af1.w };
#pragma unroll
            for (int i = 0; i < 8; i++) {
                ull a2 = pack2(am[i], am[i]);
#pragma unroll
                for (int j = 0; j < 4; j++) fma2(acc[i][j], a2, b2[j]);
            }
        }
    }
    float* C = g_cur + (size_t)m0 * R_SZ + n0;
#pragma unroll
    for (int i = 0; i < 8; i++) {
        int m = ty * 8 + i;
#pragma unroll
        for (int j = 0; j < 4; j++) {
            float2 v = unpack2(acc[i][j]);
            int n = tx * 8 + j * 2;
            C[(size_t)m * R_SZ + n]     = v.x + __ldg(bin + n0 + n);
            C[(size_t)m * R_SZ + n + 1] = v.y + __ldg(bin + n0 + n + 1);
        }
    }
}

// ---------------- per-step recurrent GEMM (R13 engine) + fused update epilogue ----
// grid (16 nt, 2 mt, nsplit), 256 threads. CTA: 64m x 64n, K = 256 chunk.
// ks<4: spk(t-1)@Wrec^T chunk ks*256 ; ks>=4: spk(t-PS)@Wlin^T chunk (ks-4)*256.
// After storing its partial, each CTA arrives on g_cnt[t*32 + mt*16 + nt]; the
// LAST arriver sums partials ks-ascending (== old k_update association exactly)
// and performs the syn/mem/spike update for its 64x64 region.
__global__ void __launch_bounds__(256)
k_step_gemm(int t, int nsplit,
            const float* __restrict__ Wrec,
            const float* __restrict__ Wlin,
            const float* __restrict__ brec,
            float* __restrict__ spk_out) {
    const int ks = blockIdx.z;
    const int nt = blockIdx.x;
    const int mt = blockIdx.y;
    const int tid = threadIdx.x;

    const int tsrc = (ks < 4) ? (t - 1) : (t - PS);
    const int kofs = (ks & 3) * GK;
    const float* Asrc = g_spk + (size_t)tsrc * BR + (size_t)(mt * 64) * R_SZ + kofs;
    const float* Wsrc = ((ks < 4) ? Wrec : Wlin) + (size_t)(nt * 64) * R_SZ + kofs;

    __shared__ float As[2][32 * TSTRIDE];
    __shared__ float Ws[2][32 * TSTRIDE];
    __shared__ unsigned old_s;

    // load mapping: row = tid>>2 (0..63), 4 threads cover 32 k as 2 float4 each
    const int lrw = tid >> 2;
    const int lkq = (tid & 3) * 2;

    const int tx = tid & 15, ty = tid >> 4;

    ull acc[4][2];
#pragma unroll
    for (int i = 0; i < 4; i++) { acc[i][0] = 0ULL; acc[i][1] = 0ULL; }

    // prefetch + store stage 0
    float4 ar[2], wr[2];
#pragma unroll
    for (int j = 0; j < 2; j++) {
        ar[j] = *(const float4*)(Asrc + (size_t)lrw * R_SZ + (lkq + j) * 4);
        wr[j] = *(const float4*)(Wsrc + (size_t)lrw * R_SZ + (lkq + j) * 4);
    }
#pragma unroll
    for (int j = 0; j < 2; j++) {
        int kk = (lkq + j) * 4;
        As[0][(kk + 0) * TSTRIDE + lrw] = ar[j].x;
        As[0][(kk + 1) * TSTRIDE + lrw] = ar[j].y;
        As[0][(kk + 2) * TSTRIDE + lrw] = ar[j].z;
        As[0][(kk + 3) * TSTRIDE + lrw] = ar[j].w;
        Ws[0][(kk + 0) * TSTRIDE + lrw] = wr[j].x;
        Ws[0][(kk + 1) * TSTRIDE + lrw] = wr[j].y;
        Ws[0][(kk + 2) * TSTRIDE + lrw] = wr[j].z;
        Ws[0][(kk + 3) * TSTRIDE + lrw] = wr[j].w;
    }
    __syncthreads();

#pragma unroll
    for (int s = 0; s < 8; s++) {
        if (s + 1 < 8) {
            const float* An = Asrc + (size_t)lrw * R_SZ + (s + 1) * 32;
            const float* Wn = Wsrc + (size_t)lrw * R_SZ + (s + 1) * 32;
#pragma unroll
            for (int j = 0; j < 2; j++) {
                ar[j] = *(const float4*)(An + (lkq + j) * 4);
                wr[j] = *(const float4*)(Wn + (lkq + j) * 4);
            }
        }
        const float* a_ = As[s & 1];
        const float* w_ = Ws[s & 1];
#pragma unroll 8
        for (int kk = 0; kk < 32; kk++) {
            float4 a = *(const float4*)(a_ + kk * TSTRIDE + ty * 4);
            float4 w = *(const float4*)(w_ + kk * TSTRIDE + tx * 4);
            ull wb0 = pack2(w.x, w.y);
            ull wb1 = pack2(w.z, w.w);
            float am4[4] = { a.x, a.y, a.z, a.w };
#pragma unroll
            for (int i = 0; i < 4; i++) {
                ull a2 = pack2(am4[i], am4[i]);
                fma2(acc[i][0], a2, wb0);
                fma2(acc[i][1], a2, wb1);
            }
        }
        if (s + 1 < 8) {
            float* ad = As[(s + 1) & 1];
            float* wd = Ws[(s + 1) & 1];
#pragma unroll
            for (int j = 0; j < 2; j++) {
                int kk = (lkq + j) * 4;
                ad[(kk + 0) * TSTRIDE + lrw] = ar[j].x;
                ad[(kk + 1) * TSTRIDE + lrw] = ar[j].y;
                ad[(kk + 2) * TSTRIDE + lrw] = ar[j].z;
                ad[(kk + 3) * TSTRIDE + lrw] = ar[j].w;
                wd[(kk + 0) * TSTRIDE + lrw] = wr[j].x;
                wd[(kk + 1) * TSTRIDE + lrw] = wr[j].y;
                wd[(kk + 2) * TSTRIDE + lrw] = wr[j].z;
                wd[(kk + 3) * TSTRIDE + lrw] = wr[j].w;
            }
        }
        __syncthreads();
    }

    // ---- store partial tile ----
    {
        float* C = g_part + (size_t)ks * BR + (size_t)(mt * 64) * R_SZ + nt * 64;
#pragma unroll
        for (int i = 0; i < 4; i++) {
            int m = ty * 4 + i;
            float2 v01 = unpack2(acc[i][0]);
            float2 v23 = unpack2(acc[i][1]);
            float4 v = make_float4(v01.x, v01.y, v23.x, v23.y);
            *(float4*)(C + (size_t)m * R_SZ + tx * 4) = v;
        }
    }

    // ---- arrival on region counter ----
    __threadfence();
    __syncthreads();
    if (tid == 0)
        old_s = atomicAdd(&g_cnt[t * 32 + mt * 16 + nt], 1u);
    __syncthreads();
    if (old_s != (unsigned)(nsplit - 1)) return;

    // ---- LAST arriver: fused state update for region (mt*64 rows, nt*64 cols) ----
    __threadfence();
    const int row = tid >> 2;            // 0..63 (m within region)
    const int colq = (tid & 3) * 16;     // 0,16,32,48 (n offset within region)
    const int m = mt * 64 + row;
    const int ng = nt * 64 + colq;
    const size_t ebase = (size_t)m * R_SZ + ng;

#pragma unroll
    for (int j = 0; j < 4; j++) {
        size_t idx = ebase + j * 4;
        int r = (int)(idx & (R_SZ - 1));

        float4 cur = *(const float4*)(g_cur + (size_t)t * BR + idx);
        float4 s = make_float4(0.f, 0.f, 0.f, 0.f);
        if (nsplit == 8) {
#pragma unroll
            for (int k2 = 0; k2 < 8; k2++) {
                float4 pv = *(const float4*)(g_part + (size_t)k2 * BR + idx);
                s.x += pv.x; s.y += pv.y; s.z += pv.z; s.w += pv.w;
            }
        } else {
#pragma unroll
            for (int k2 = 0; k2 < 4; k2++) {
                float4 pv = *(const float4*)(g_part + (size_t)k2 * BR + idx);
                s.x += pv.x; s.y += pv.y; s.z += pv.z; s.w += pv.w;
            }
        }
        float4 br  = *(const float4*)(brec + r);
        float4 syn = *(float4*)(g_syn + idx);
        float4 mem = *(float4*)(g_mem + idx);

        float4 spk;
        syn.x = ALPHA * syn.x + cur.x + s.x + br.x;
        float rs = (mem.x > 1.0f) ? 1.0f : 0.0f;
        mem.x = BETA * mem.x + syn.x - rs;
        spk.x = (mem.x > 1.0f) ? 1.0f : 0.0f;

        syn.y = ALPHA * syn.y + cur.y + s.y + br.y;
        rs = (mem.y > 1.0f) ? 1.0f : 0.0f;
        mem.y = BETA * mem.y + syn.y - rs;
        spk.y = (mem.y > 1.0f) ? 1.0f : 0.0f;

        syn.z = ALPHA * syn.z + cur.z + s.z + br.z;
        rs = (mem.z > 1.0f) ? 1.0f : 0.0f;
        mem.z = BETA * mem.z + syn.z - rs;
        spk.z = (mem.z > 1.0f) ? 1.0f : 0.0f;

        syn.w = ALPHA * syn.w + cur.w + s.w + br.w;
        rs = (mem.w > 1.0f) ? 1.0f : 0.0f;
        mem.w = BETA * mem.w + syn.w - rs;
        spk.w = (mem.w > 1.0f) ? 1.0f : 0.0f;

        *(float4*)(g_syn + idx) = syn;
        *(float4*)(g_mem + idx) = mem;
        *(float4*)(g_spk + (size_t)t * BR + idx) = spk;
        if (spk_out) *(float4*)(spk_out + (size_t)t * BR + idx) = spk;
    }
}

// ---------------- standalone state update (t=0 only: no gemm CTAs) ----------------
__global__ void k_update0(float* __restrict__ spk_out,
                          const float* __restrict__ brec) {
    int idx = (blockIdx.x * 256 + threadIdx.x) * 4;  // over BR
    int r = idx & (R_SZ - 1);

    float4 cur = *(const float4*)(g_cur + idx);
    float4 br  = *(const float4*)(brec + r);
    float4 syn = *(float4*)(g_syn + idx);
    float4 mem = *(float4*)(g_mem + idx);

    float4 spk;
    syn.x = ALPHA * syn.x + cur.x + br.x;
    float rs = (mem.x > 1.0f) ? 1.0f : 0.0f;
    mem.x = BETA * mem.x + syn.x - rs;
    spk.x = (mem.x > 1.0f) ? 1.0f : 0.0f;

    syn.y = ALPHA * syn.y + cur.y + br.y;
    rs = (mem.y > 1.0f) ? 1.0f : 0.0f;
    mem.y = BETA * mem.y + syn.y - rs;
    spk.y = (mem.y > 1.0f) ? 1.0f : 0.0f;

    syn.z = ALPHA * syn.z + cur.z + br.z;
    rs = (mem.z > 1.0f) ? 1.0f : 0.0f;
    mem.z = BETA * mem.z + syn.z - rs;
    spk.z = (mem.z > 1.0f) ? 1.0f : 0.0f;

    syn.w = ALPHA * syn.w + cur.w + br.w;
    rs = (mem.w > 1.0f) ? 1.0f : 0.0f;
    mem.w = BETA * mem.w + syn.w - rs;
    spk.w = (mem.w > 1.0f) ? 1.0f : 0.0f;

    *(float4*)(g_syn + idx) = syn;
    *(float4*)(g_mem + idx) = mem;
    *(float4*)(g_spk + idx) = spk;
    if (spk_out) *(float4*)(spk_out + idx) = spk;
}

// ---------------- readout mean over each partition ----------------
__global__ void k_ro_reduce() {
    int e = (blockIdx.x * 256 + threadIdx.x) * 4;   // over B*3R = 393216
    int b = e / (3 * R_SZ);
    int c = e % (3 * R_SZ);
    int p = c >> 10;
    int r = c & (R_SZ - 1);
    const float* base = g_spk + ((size_t)(p * PS) * B_SZ + b) * R_SZ + r;
    float4 s = make_float4(0.f, 0.f, 0.f, 0.f);
#pragma unroll 8
    for (int st = 0; st < PS; st++) {
        float4 v = *(const float4*)(base + (size_t)st * BR);
        s.x += v.x; s.y += v.y; s.z += v.z; s.w += v.w;
    }
    float inv = 1.0f / (float)PS;
    s.x *= inv; s.y *= inv; s.z *= inv; s.w *= inv;
    *(float4*)(g_ro + e) = s;
}

// ---------------- final readout GEMM + softmax ----------------
__global__ void k_readout(float* __restrict__ out,
                          const float* __restrict__ Wro,
                          const float* __restrict__ bro) {
    int b = blockIdx.x;
    __shared__ float ro_s[3 * R_SZ];
    __shared__ float logit[112];
    __shared__ float red_sum;
    int tid = threadIdx.x;  // 128 threads

    for (int i = tid * 4; i < 3 * R_SZ; i += 512)
        *(float4*)&ro_s[i] = *(const float4*)(g_ro + (size_t)b * 3 * R_SZ + i);
    __syncthreads();

    int warp = tid >> 5, lane = tid & 31;
    for (int o = warp; o < OUT_SZ; o += 4) {
        const float* w = Wro + (size_t)o * (3 * R_SZ);
        float p0 = 0.f;
        for (int k = lane; k < 3 * R_SZ; k += 32) p0 += ro_s[k] * __ldg(w + k);
#pragma unroll
        for (int off = 16; off; off >>= 1) p0 += __shfl_xor_sync(0xffffffffu, p0, off);
        if (lane == 0) logit[o] = p0 + __ldg(bro + o);
    }
    __syncthreads();
    if (warp == 0) {
        float m = -1e30f;
        for (int i = lane; i < OUT_SZ; i += 32) m = fmaxf(m, logit[i]);
#pragma unroll
        for (int off = 16; off; off >>= 1) m = fmaxf(m, __shfl_xor_sync(0xffffffffu, m, off));
        float sm = 0.f;
        for (int i = lane; i < OUT_SZ; i += 32) {
            float e = expf(logit[i] - m);
            logit[i] = e;
            sm += e;
        }
#pragma unroll
        for (int off = 16; off; off >>= 1) sm += __shfl_xor_sync(0xffffffffu, sm, off);
        if (lane == 0) red_sum = sm;
    }
    __syncthreads();
    float inv = 1.0f / red_sum;
    for (int i = tid; i < OUT_SZ; i += 128)
        out[(size_t)b * OUT_SZ + i] = logit[i] * inv;
}

// ---------------- launcher ----------------
extern "C" void kernel_launch(void* const* d_in, const int* in_sizes, int n_in,
                              void* d_out, int out_size) {
    const float* x     = (const float*)d_in[0];
    const float* W_in  = (const float*)d_in[1];
    const float* b_in  = (const float*)d_in[2];
    const float* W_lin = (const float*)d_in[3];
    const float* W_rec = (const float*)d_in[4];
    const float* b_rec = (const float*)d_in[5];
    const float* W_ro  = (const float*)d_in[6];
    const float* b_ro  = (const float*)d_in[7];

    float* out_main = (float*)d_out;
    float* spk_out  = nullptr;
    if (out_size >= OUT_ELEMS + SPK_ELEMS) {
        spk_out = (float*)d_out + OUT_ELEMS;
    } else if (out_size == SPK_ELEMS) {
        spk_out = (float*)d_out;
        out_main = nullptr;
    }

    k_init<<<128, 256>>>();
    k_input_gemm<<<dim3(R_SZ / 128, (T_STEPS * B_SZ) / 128), 256>>>(x, W_in, b_in);

    k_update0<<<128, 256>>>(spk_out, b_rec);   // t = 0 (no recurrent input)

    for (int t = 1; t < T_STEPS; t++) {
        int nsplit = (t > PS) ? 8 : 4;
        k_step_gemm<<<dim3(16, 2, nsplit), 256>>>(t, nsplit, W_rec, W_lin, b_rec, spk_out);
    }

    k_ro_reduce<<<384, 256>>>();
    if (out_main) k_readout<<<B_SZ, 128>>>(out_main, W_ro, b_ro);
}

// round 16
// speedup vs baseline: 1.2472x; 1.2472x over previous
#include <cuda_runtime.h>

// ---------------- problem constants ----------------
#define T_STEPS 192
#define B_SZ    128
#define IN_SZ   512
#define R_SZ    1024
#define OUT_SZ  100
#define PS      64
#define BR      (B_SZ * R_SZ)          // 131072
#define SPK_ELEMS (T_STEPS * BR)       // 25165824
#define OUT_ELEMS (B_SZ * OUT_SZ)      // 12800
#define ALPHA 0.9f
#define BETA  0.9f

#define GK 256                 // K per split chunk (association FROZEN)
#define NSPLIT_MAX 8
#define TSTRIDE 68             // smem row stride (64 + pad)

// ---------------- device scratch ----------------
__device__ float g_cur[T_STEPS * BR];    // input projection (+b_in)
__device__ float g_spk[T_STEPS * BR];    // spike history fp32
__device__ float g_syn[BR];
__device__ float g_mem[BR];
__device__ float g_part[NSPLIT_MAX * BR];// split-K partials
__device__ float g_ro[B_SZ * 3 * R_SZ];  // readout input

typedef unsigned long long ull;

__device__ __forceinline__ ull pack2(float lo, float hi) {
    ull r; asm("mov.b64 %0, {%1,%2};" : "=l"(r) : "f"(lo), "f"(hi)); return r;
}
__device__ __forceinline__ void fma2(ull &d, ull a, ull b) {
    asm("fma.rn.f32x2 %0, %1, %2, %0;" : "+l"(d) : "l"(a), "l"(b));
}
__device__ __forceinline__ float2 unpack2(ull v) {
    float2 r; asm("mov.b64 {%0,%1}, %2;" : "=f"(r.x), "=f"(r.y) : "l"(v)); return r;
}

// ---------------- init: zero syn/mem ----------------
__global__ void k_init() {
    int i = blockIdx.x * blockDim.x + threadIdx.x;
    float4 z = make_float4(0.f, 0.f, 0.f, 0.f);
    *(float4*)(g_syn + i * 4) = z;
    *(float4*)(g_mem + i * 4) = z;
}

// ---------------- input projection GEMM (R1 engine, chunked over t) ----------------
// mb0 = m-block offset (each m-block = 128 rows of T*B). Per-element arithmetic
// identical to the monolithic launch; only the grid slicing changes.
__global__ void k_input_gemm(const float* __restrict__ X,
                             const float* __restrict__ Win,
                             const float* __restrict__ bin,
                             int mb0) {
    __shared__ float As[16][128];
    __shared__ float Bs[16][128];
    int tid = threadIdx.x;
    int n0 = blockIdx.x * 128;
    int m0 = (blockIdx.y + mb0) * 128;
    int p  = m0 >> 13;
    const float* A = X + (size_t)m0 * IN_SZ;
    const float* W = Win + (size_t)p * R_SZ * IN_SZ + (size_t)n0 * IN_SZ;

    int lr = tid >> 2;
    int lk = (tid & 3) * 4;
    int tx = tid & 15, ty = tid >> 4;

    ull acc[8][4];
#pragma unroll
    for (int i = 0; i < 8; i++)
#pragma unroll
        for (int j = 0; j < 4; j++) acc[i][j] = 0ULL;

    for (int k0 = 0; k0 < IN_SZ; k0 += 16) {
        float4 a0 = *(const float4*)(A + (size_t)lr * IN_SZ + k0 + lk);
        float4 a1 = *(const float4*)(A + (size_t)(lr + 64) * IN_SZ + k0 + lk);
        float4 b0 = *(const float4*)(W + (size_t)lr * IN_SZ + k0 + lk);
        float4 b1 = *(const float4*)(W + (size_t)(lr + 64) * IN_SZ + k0 + lk);
        __syncthreads();
        As[lk + 0][lr] = a0.x; As[lk + 1][lr] = a0.y; As[lk + 2][lr] = a0.z; As[lk + 3][lr] = a0.w;
        As[lk + 0][lr + 64] = a1.x; As[lk + 1][lr + 64] = a1.y; As[lk + 2][lr + 64] = a1.z; As[lk + 3][lr + 64] = a1.w;
        Bs[lk + 0][lr] = b0.x; Bs[lk + 1][lr] = b0.y; Bs[lk + 2][lr] = b0.z; Bs[lk + 3][lr] = b0.w;
        Bs[lk + 0][lr + 64] = b1.x; Bs[lk + 1][lr + 64] = b1.y; Bs[lk + 2][lr + 64] = b1.z; Bs[lk + 3][lr + 64] = b1.w;
        __syncthreads();
#pragma unroll
        for (int kk = 0; kk < 16; kk++) {
            float4 af0 = *(float4*)&As[kk][ty * 8];
            float4 af1 = *(float4*)&As[kk][ty * 8 + 4];
            float4 bf0 = *(float4*)&Bs[kk][tx * 8];
            float4 bf1 = *(float4*)&Bs[kk][tx * 8 + 4];
            ull b2[4] = { pack2(bf0.x, bf0.y), pack2(bf0.z, bf0.w),
                          pack2(bf1.x, bf1.y), pack2(bf1.z, bf1.w) };
            float am[8] = { af0.x, af0.y, af0.z, af0.w, af1.x, af1.y, af1.z, af1.w };
#pragma unroll
            for (int i = 0; i < 8; i++) {
                ull a2 = pack2(am[i], am[i]);
#pragma unroll
                for (int j = 0; j < 4; j++) fma2(acc[i][j], a2, b2[j]);
            }
        }
    }
    float* C = g_cur + (size_t)m0 * R_SZ + n0;
#pragma unroll
    for (int i = 0; i < 8; i++) {
        int m = ty * 8 + i;
#pragma unroll
        for (int j = 0; j < 4; j++) {
            float2 v = unpack2(acc[i][j]);
            int n = tx * 8 + j * 2;
            C[(size_t)m * R_SZ + n]     = v.x + __ldg(bin + n0 + n);
            C[(size_t)m * R_SZ + n + 1] = v.y + __ldg(bin + n0 + n + 1);
        }
    }
}

// ---------------- per-step recurrent GEMM (R13 verbatim) ----------------
// grid (16 nt, 2 mt, nsplit), 256 threads. CTA: 64m x 64n, K = 256 chunk.
__global__ void __launch_bounds__(256)
k_step_gemm(int t,
            const float* __restrict__ Wrec,
            const float* __restrict__ Wlin) {
    const int ks = blockIdx.z;
    const int nt = blockIdx.x;
    const int mt = blockIdx.y;
    const int tid = threadIdx.x;

    const int tsrc = (ks < 4) ? (t - 1) : (t - PS);
    const int kofs = (ks & 3) * GK;
    const float* Asrc = g_spk + (size_t)tsrc * BR + (size_t)(mt * 64) * R_SZ + kofs;
    const float* Wsrc = ((ks < 4) ? Wrec : Wlin) + (size_t)(nt * 64) * R_SZ + kofs;

    __shared__ float As[2][32 * TSTRIDE];
    __shared__ float Ws[2][32 * TSTRIDE];

    const int lrw = tid >> 2;
    const int lkq = (tid & 3) * 2;

    const int tx = tid & 15, ty = tid >> 4;

    ull acc[4][2];
#pragma unroll
    for (int i = 0; i < 4; i++) { acc[i][0] = 0ULL; acc[i][1] = 0ULL; }

    float4 ar[2], wr[2];
#pragma unroll
    for (int j = 0; j < 2; j++) {
        ar[j] = *(const float4*)(Asrc + (size_t)lrw * R_SZ + (lkq + j) * 4);
        wr[j] = *(const float4*)(Wsrc + (size_t)lrw * R_SZ + (lkq + j) * 4);
    }
#pragma unroll
    for (int j = 0; j < 2; j++) {
        int kk = (lkq + j) * 4;
        As[0][(kk + 0) * TSTRIDE + lrw] = ar[j].x;
        As[0][(kk + 1) * TSTRIDE + lrw] = ar[j].y;
        As[0][(kk + 2) * TSTRIDE + lrw] = ar[j].z;
        As[0][(kk + 3) * TSTRIDE + lrw] = ar[j].w;
        Ws[0][(kk + 0) * TSTRIDE + lrw] = wr[j].x;
        Ws[0][(kk + 1) * TSTRIDE + lrw] = wr[j].y;
        Ws[0][(kk + 2) * TSTRIDE + lrw] = wr[j].z;
        Ws[0][(kk + 3) * TSTRIDE + lrw] = wr[j].w;
    }
    __syncthreads();

#pragma unroll
    for (int s = 0; s < 8; s++) {
        if (s + 1 < 8) {
            const float* An = Asrc + (size_t)lrw * R_SZ + (s + 1) * 32;
            const float* Wn = Wsrc + (size_t)lrw * R_SZ + (s + 1) * 32;
#pragma unroll
            for (int j = 0; j < 2; j++) {
                ar[j] = *(const float4*)(An + (lkq + j) * 4);
                wr[j] = *(const float4*)(Wn + (lkq + j) * 4);
            }
        }
        const float* a_ = As[s & 1];
        const float* w_ = Ws[s & 1];
#pragma unroll 8
        for (int kk = 0; kk < 32; kk++) {
            float4 a = *(const float4*)(a_ + kk * TSTRIDE + ty * 4);
            float4 w = *(const float4*)(w_ + kk * TSTRIDE + tx * 4);
            ull wb0 = pack2(w.x, w.y);
            ull wb1 = pack2(w.z, w.w);
            float am4[4] = { a.x, a.y, a.z, a.w };
#pragma unroll
            for (int i = 0; i < 4; i++) {
                ull a2 = pack2(am4[i], am4[i]);
                fma2(acc[i][0], a2, wb0);
                fma2(acc[i][1], a2, wb1);
            }
        }
        if (s + 1 < 8) {
            float* ad = As[(s + 1) & 1];
            float* wd = Ws[(s + 1) & 1];
#pragma unroll
            for (int j = 0; j < 2; j++) {
                int kk = (lkq + j) * 4;
                ad[(kk + 0) * TSTRIDE + lrw] = ar[j].x;
                ad[(kk + 1) * TSTRIDE + lrw] = ar[j].y;
                ad[(kk + 2) * TSTRIDE + lrw] = ar[j].z;
                ad[(kk + 3) * TSTRIDE + lrw] = ar[j].w;
                wd[(kk + 0) * TSTRIDE + lrw] = wr[j].x;
                wd[(kk + 1) * TSTRIDE + lrw] = wr[j].y;
                wd[(kk + 2) * TSTRIDE + lrw] = wr[j].z;
                wd[(kk + 3) * TSTRIDE + lrw] = wr[j].w;
            }
        }
        __syncthreads();
    }

    float* C = g_part + (size_t)ks * BR + (size_t)(mt * 64) * R_SZ + nt * 64;
#pragma unroll
    for (int i = 0; i < 4; i++) {
        int m = ty * 4 + i;
        float2 v01 = unpack2(acc[i][0]);
        float2 v23 = unpack2(acc[i][1]);
        float4 v = make_float4(v01.x, v01.y, v23.x, v23.y);
        *(float4*)(C + (size_t)m * R_SZ + tx * 4) = v;
    }
}

// ---------------- per-step state update (R13 verbatim) ----------------
__global__ void k_update(int t, int nsplit, float* __restrict__ spk_out,
                         const float* __restrict__ brec) {
    int idx = (blockIdx.x * 256 + threadIdx.x) * 2;  // over BR, grid 256
    int r = idx & (R_SZ - 1);

    float2 cur = *(const float2*)(g_cur + (size_t)t * BR + idx);
    float2 s = make_float2(0.f, 0.f);
    if (nsplit == 8) {
#pragma unroll
        for (int ks = 0; ks < 8; ks++) {
            float2 pv = *(const float2*)(g_part + (size_t)ks * BR + idx);
            s.x += pv.x; s.y += pv.y;
        }
    } else if (nsplit == 4) {
#pragma unroll
        for (int ks = 0; ks < 4; ks++) {
            float2 pv = *(const float2*)(g_part + (size_t)ks * BR + idx);
            s.x += pv.x; s.y += pv.y;
        }
    }
    float2 br  = *(const float2*)(brec + r);
    float2 syn = *(float2*)(g_syn + idx);
    float2 mem = *(float2*)(g_mem + idx);

    float2 spk;
    syn.x = ALPHA * syn.x + cur.x + s.x + br.x;
    float rs = (mem.x > 1.0f) ? 1.0f : 0.0f;
    mem.x = BETA * mem.x + syn.x - rs;
    spk.x = (mem.x > 1.0f) ? 1.0f : 0.0f;

    syn.y = ALPHA * syn.y + cur.y + s.y + br.y;
    rs = (mem.y > 1.0f) ? 1.0f : 0.0f;
    mem.y = BETA * mem.y + syn.y - rs;
    spk.y = (mem.y > 1.0f) ? 1.0f : 0.0f;

    *(float2*)(g_syn + idx) = syn;
    *(float2*)(g_mem + idx) = mem;
    *(float2*)(g_spk + (size_t)t * BR + idx) = spk;
    if (spk_out) *(float2*)(spk_out + (size_t)t * BR + idx) = spk;
}

// ---------------- readout mean over each partition ----------------
__global__ void k_ro_reduce() {
    int e = (blockIdx.x * 256 + threadIdx.x) * 4;   // over B*3R = 393216
    int b = e / (3 * R_SZ);
    int c = e % (3 * R_SZ);
    int p = c >> 10;
    int r = c & (R_SZ - 1);
    const float* base = g_spk + ((size_t)(p * PS) * B_SZ + b) * R_SZ + r;
    float4 s = make_float4(0.f, 0.f, 0.f, 0.f);
#pragma unroll 8
    for (int st = 0; st < PS; st++) {
        float4 v = *(const float4*)(base + (size_t)st * BR);
        s.x += v.x; s.y += v.y; s.z += v.z; s.w += v.w;
    }
    float inv = 1.0f / (float)PS;
    s.x *= inv; s.y *= inv; s.z *= inv; s.w *= inv;
    *(float4*)(g_ro + e) = s;
}

// ---------------- final readout GEMM + softmax ----------------
__global__ void k_readout(float* __restrict__ out,
                          const float* __restrict__ Wro,
                          const float* __restrict__ bro) {
    int b = blockIdx.x;
    __shared__ float ro_s[3 * R_SZ];
    __shared__ float logit[112];
    __shared__ float red_sum;
    int tid = threadIdx.x;  // 128 threads

    for (int i = tid * 4; i < 3 * R_SZ; i += 512)
        *(float4*)&ro_s[i] = *(const float4*)(g_ro + (size_t)b * 3 * R_SZ + i);
    __syncthreads();

    int warp = tid >> 5, lane = tid & 31;
    for (int o = warp; o < OUT_SZ; o += 4) {
        const float* w = Wro + (size_t)o * (3 * R_SZ);
        float p0 = 0.f;
        for (int k = lane; k < 3 * R_SZ; k += 32) p0 += ro_s[k] * __ldg(w + k);
#pragma unroll
        for (int off = 16; off; off >>= 1) p0 += __shfl_xor_sync(0xffffffffu, p0, off);
        if (lane == 0) logit[o] = p0 + __ldg(bro + o);
    }
    __syncthreads();
    if (warp == 0) {
        float m = -1e30f;
        for (int i = lane; i < OUT_SZ; i += 32) m = fmaxf(m, logit[i]);
#pragma unroll
        for (int off = 16; off; off >>= 1) m = fmaxf(m, __shfl_xor_sync(0xffffffffu, m, off));
        float sm = 0.f;
        for (int i = lane; i < OUT_SZ; i += 32) {
            float e = expf(logit[i] - m);
            logit[i] = e;
            sm += e;
        }
#pragma unroll
        for (int off = 16; off; off >>= 1) sm += __shfl_xor_sync(0xffffffffu, sm, off);
        if (lane == 0) red_sum = sm;
    }
    __syncthreads();
    float inv = 1.0f / red_sum;
    for (int i = tid; i < OUT_SZ; i += 128)
        out[(size_t)b * OUT_SZ + i] = logit[i] * inv;
}

// ---------------- launcher (multi-stream: input GEMM overlapped with scan) ----
#define N_CHUNK 4
// chunk c covers t in [CHUNK_T0[c], CHUNK_T0[c+1])
static const int CHUNK_T0[N_CHUNK + 1] = { 0, 16, 48, 96, 192 };

extern "C" void kernel_launch(void* const* d_in, const int* in_sizes, int n_in,
                              void* d_out, int out_size) {
    const float* x     = (const float*)d_in[0];
    const float* W_in  = (const float*)d_in[1];
    const float* b_in  = (const float*)d_in[2];
    const float* W_lin = (const float*)d_in[3];
    const float* W_rec = (const float*)d_in[4];
    const float* b_rec = (const float*)d_in[5];
    const float* W_ro  = (const float*)d_in[6];
    const float* b_ro  = (const float*)d_in[7];

    float* out_main = (float*)d_out;
    float* spk_out  = nullptr;
    if (out_size >= OUT_ELEMS + SPK_ELEMS) {
        spk_out = (float*)d_out + OUT_ELEMS;
    } else if (out_size == SPK_ELEMS) {
        spk_out = (float*)d_out;
        out_main = nullptr;
    }

    // one-time stream/event resources (created outside capture on first call)
    static cudaStream_t s2 = nullptr;
    static cudaEvent_t evFork = nullptr;
    static cudaEvent_t evChunk[N_CHUNK];
    if (!s2) {
        cudaStreamCreateWithFlags(&s2, cudaStreamNonBlocking);
        cudaEventCreateWithFlags(&evFork, cudaEventDisableTiming);
        for (int c = 0; c < N_CHUNK; c++)
            cudaEventCreateWithFlags(&evChunk[c], cudaEventDisableTiming);
    }

    // main (capture) stream = default stream 0
    k_init<<<128, 256>>>();

    // fork: input projection chunks run on s2, overlapping the scan
    cudaEventRecord(evFork, 0);
    cudaStreamWaitEvent(s2, evFork, 0);
    for (int c = 0; c < N_CHUNK; c++) {
        int mb0 = CHUNK_T0[c];                 // 1 m-block (128 rows) per t
        int nmb = CHUNK_T0[c + 1] - CHUNK_T0[c];
        k_input_gemm<<<dim3(R_SZ / 128, nmb), 256, 0, s2>>>(x, W_in, b_in, mb0);
        cudaEventRecord(evChunk[c], s2);
    }

    int next_chunk = 0;
    for (int t = 0; t < T_STEPS; t++) {
        // before first step of each chunk, join that chunk's input GEMM
        while (next_chunk < N_CHUNK && t == CHUNK_T0[next_chunk]) {
            cudaStreamWaitEvent(0, evChunk[next_chunk], 0);
            next_chunk++;
        }
        int nsplit = (t == 0) ? 0 : ((t > PS) ? 8 : 4);
        if (nsplit)
            k_step_gemm<<<dim3(16, 2, nsplit), 256>>>(t, W_rec, W_lin);
        k_update<<<256, 256>>>(t, nsplit, spk_out, b_rec);
    }

    k_ro_reduce<<<384, 256>>>();
    if (out_main) k_readout<<<B_SZ, 128>>>(out_main, W_ro, b_ro);
}